// round 7
// baseline (speedup 1.0000x reference)
#include <cuda_runtime.h>

#define BATCH 16
#define CHN   64
#define HW    65536
#define HW4   (HW / 4)
#define NBLK  64   // pass1 blocks per batch

// Per-(batch, block) partials, written fresh each launch (no zeroing):
// [0]=max_s [1]=max_sq [2]=mean_s [3]=mean_sq [4]=min_s [5]=min_sq [6]=cnt [7]=pad
__device__ float g_part[BATCH][NBLK][8];
// Final per-batch stats: mean0,rstd0,mean1,rstd1,mean2,rstd2,pad,pad
__device__ float g_stats[BATCH][8];
// Per-batch arrival tickets (self-resetting).
__device__ unsigned g_cnt[BATCH] = {0};

__device__ __forceinline__ float warp_sum(float v) {
#pragma unroll
    for (int o = 16; o; o >>= 1) v += __shfl_xor_sync(0xffffffffu, v, o);
    return v;
}

// Pass 1: channel pool + masked partial sums; LAST block per batch finalizes stats.
__global__ void __launch_bounds__(256) pool_k(
    const float* __restrict__ x,
    const int*   __restrict__ mask,
    float*       __restrict__ out)
{
    const int b  = blockIdx.y;
    const int p4 = blockIdx.x * 256 + threadIdx.x;

    const float4* xb = reinterpret_cast<const float4*>(x) + (size_t)b * CHN * HW4 + p4;

    float4 v = __ldcs(&xb[0]);
    float4 vmax = v, vmin = v, vsum = v;
#pragma unroll
    for (int c = 1; c < CHN; ++c) {
        float4 t = __ldcs(&xb[(size_t)c * HW4]);
        vmax.x = fmaxf(vmax.x, t.x); vmax.y = fmaxf(vmax.y, t.y);
        vmax.z = fmaxf(vmax.z, t.z); vmax.w = fmaxf(vmax.w, t.w);
        vmin.x = fminf(vmin.x, t.x); vmin.y = fminf(vmin.y, t.y);
        vmin.z = fminf(vmin.z, t.z); vmin.w = fminf(vmin.w, t.w);
        vsum.x += t.x; vsum.y += t.y; vsum.z += t.z; vsum.w += t.w;
    }
    const float inv = 1.f / (float)CHN;
    float4 vmean = make_float4(vsum.x * inv, vsum.y * inv, vsum.z * inv, vsum.w * inv);

    float4* ob = reinterpret_cast<float4*>(out) + (size_t)b * 3 * HW4 + p4;
    ob[0]       = vmax;
    ob[HW4]     = vmean;
    ob[2 * HW4] = vmin;

    int4 mk = reinterpret_cast<const int4*>(mask)[(size_t)b * HW4 + p4];
    float m0 = (mk.x == 1) ? 1.f : 0.f;
    float m1 = (mk.y == 1) ? 1.f : 0.f;
    float m2 = (mk.z == 1) ? 1.f : 0.f;
    float m3 = (mk.w == 1) ? 1.f : 0.f;

    float vals[7];
    vals[0] = vmax.x  * m0 + vmax.y  * m1 + vmax.z  * m2 + vmax.w  * m3;
    vals[1] = vmax.x * vmax.x * m0 + vmax.y * vmax.y * m1
            + vmax.z * vmax.z * m2 + vmax.w * vmax.w * m3;
    vals[2] = vmean.x * m0 + vmean.y * m1 + vmean.z * m2 + vmean.w * m3;
    vals[3] = vmean.x * vmean.x * m0 + vmean.y * vmean.y * m1
            + vmean.z * vmean.z * m2 + vmean.w * vmean.w * m3;
    vals[4] = vmin.x  * m0 + vmin.y  * m1 + vmin.z  * m2 + vmin.w  * m3;
    vals[5] = vmin.x * vmin.x * m0 + vmin.y * vmin.y * m1
            + vmin.z * vmin.z * m2 + vmin.w * vmin.w * m3;
    vals[6] = m0 + m1 + m2 + m3;

    __shared__ float sh[8][7];
    const int lane = threadIdx.x & 31;
    const int wid  = threadIdx.x >> 5;

#pragma unroll
    for (int i = 0; i < 7; ++i) vals[i] = warp_sum(vals[i]);
    if (lane == 0) {
#pragma unroll
        for (int i = 0; i < 7; ++i) sh[wid][i] = vals[i];
    }
    __syncthreads();
    if (wid == 0) {
#pragma unroll
        for (int i = 0; i < 7; ++i) {
            float t = (lane < 8) ? sh[lane][i] : 0.f;
            t = warp_sum(t);
            if (lane == 0) g_part[b][blockIdx.x][i] = t;
        }

        // ---- last-block-per-batch finalizes mean/rstd ----
        unsigned old = 0;
        if (lane == 0) {
            __threadfence();                     // publish g_part row
            old = atomicAdd(&g_cnt[b], 1);
        }
        old = __shfl_sync(0xffffffffu, old, 0);
        if (old == NBLK - 1) {
            __threadfence();                     // acquire all g_part rows
            // lane r reduces rows r and r+32 (L2 loads, bypass L1)
            const float4* r0 = reinterpret_cast<const float4*>(&g_part[b][lane][0]);
            const float4* r1 = reinterpret_cast<const float4*>(&g_part[b][lane + 32][0]);
            float4 a0 = __ldcg(&r0[0]), a1 = __ldcg(&r0[1]);
            float4 b0 = __ldcg(&r1[0]), b1 = __ldcg(&r1[1]);
            float s[7];
            s[0] = a0.x + b0.x; s[1] = a0.y + b0.y; s[2] = a0.z + b0.z;
            s[3] = a0.w + b0.w; s[4] = a1.x + b1.x; s[5] = a1.y + b1.y;
            s[6] = a1.z + b1.z;
#pragma unroll
            for (int i = 0; i < 7; ++i) s[i] = warp_sum(s[i]);
            if (lane == 0) {
                const float cnt = s[6];
#pragma unroll
                for (int ch = 0; ch < 3; ++ch) {
                    const float sm   = s[2 * ch];
                    const float sq   = s[2 * ch + 1];
                    const float mean = sm / cnt;
                    const float var  = (sq - sm * mean) / (cnt - 1.f);
                    g_stats[b][2 * ch]     = mean;
                    g_stats[b][2 * ch + 1] = rsqrtf(var);
                }
                g_cnt[b] = 0;                    // self-reset for next launch
            }
        }
    }
}

// Pass 2: normalize in place. No syncs, no prologue — stats are precomputed.
// Each thread handles 2 float4 columns x 3 channels.
__global__ void __launch_bounds__(256) norm_k(
    float*     __restrict__ out,
    const int* __restrict__ mask)
{
    const int b  = blockIdx.y;
    const int pA = blockIdx.x * 512 + threadIdx.x;
    const int pB = pA + 256;

    const float4* st4 = reinterpret_cast<const float4*>(&g_stats[b][0]);
    float4 s0 = st4[0];   // mean0, rstd0, mean1, rstd1
    float4 s1 = st4[1];   // mean2, rstd2, -, -
    const float mean0 = s0.x, rstd0 = s0.y;
    const float mean1 = s0.z, rstd1 = s0.w;
    const float mean2 = s1.x, rstd2 = s1.y;

    const int4* mb = reinterpret_cast<const int4*>(mask) + (size_t)b * HW4;
    float4*     ob = reinterpret_cast<float4*>(out)      + (size_t)b * 3 * HW4;

    // Issue everything up front for MLP.
    int4 mkA = mb[pA];
    int4 mkB = mb[pB];
    float4 a0 = ob[pA];             float4 b0 = ob[pB];
    float4 a1 = ob[HW4 + pA];       float4 b1 = ob[HW4 + pB];
    float4 a2 = ob[2 * HW4 + pA];   float4 b2 = ob[2 * HW4 + pB];

    a0.x = (mkA.x == 1) ? (a0.x - mean0) * rstd0 : 0.f;
    a0.y = (mkA.y == 1) ? (a0.y - mean0) * rstd0 : 0.f;
    a0.z = (mkA.z == 1) ? (a0.z - mean0) * rstd0 : 0.f;
    a0.w = (mkA.w == 1) ? (a0.w - mean0) * rstd0 : 0.f;
    a1.x = (mkA.x == 1) ? (a1.x - mean1) * rstd1 : 0.f;
    a1.y = (mkA.y == 1) ? (a1.y - mean1) * rstd1 : 0.f;
    a1.z = (mkA.z == 1) ? (a1.z - mean1) * rstd1 : 0.f;
    a1.w = (mkA.w == 1) ? (a1.w - mean1) * rstd1 : 0.f;
    a2.x = (mkA.x == 1) ? (a2.x - mean2) * rstd2 : 0.f;
    a2.y = (mkA.y == 1) ? (a2.y - mean2) * rstd2 : 0.f;
    a2.z = (mkA.z == 1) ? (a2.z - mean2) * rstd2 : 0.f;
    a2.w = (mkA.w == 1) ? (a2.w - mean2) * rstd2 : 0.f;

    b0.x = (mkB.x == 1) ? (b0.x - mean0) * rstd0 : 0.f;
    b0.y = (mkB.y == 1) ? (b0.y - mean0) * rstd0 : 0.f;
    b0.z = (mkB.z == 1) ? (b0.z - mean0) * rstd0 : 0.f;
    b0.w = (mkB.w == 1) ? (b0.w - mean0) * rstd0 : 0.f;
    b1.x = (mkB.x == 1) ? (b1.x - mean1) * rstd1 : 0.f;
    b1.y = (mkB.y == 1) ? (b1.y - mean1) * rstd1 : 0.f;
    b1.z = (mkB.z == 1) ? (b1.z - mean1) * rstd1 : 0.f;
    b1.w = (mkB.w == 1) ? (b1.w - mean1) * rstd1 : 0.f;
    b2.x = (mkB.x == 1) ? (b2.x - mean2) * rstd2 : 0.f;
    b2.y = (mkB.y == 1) ? (b2.y - mean2) * rstd2 : 0.f;
    b2.z = (mkB.z == 1) ? (b2.z - mean2) * rstd2 : 0.f;
    b2.w = (mkB.w == 1) ? (b2.w - mean2) * rstd2 : 0.f;

    ob[pA]           = a0;   ob[pB]           = b0;
    ob[HW4 + pA]     = a1;   ob[HW4 + pB]     = b1;
    ob[2 * HW4 + pA] = a2;   ob[2 * HW4 + pB] = b2;
}

extern "C" void kernel_launch(void* const* d_in, const int* in_sizes, int n_in,
                              void* d_out, int out_size)
{
    const float* x;
    const int*   mask;
    if (in_sizes[0] > in_sizes[1]) {
        x    = (const float*)d_in[0];
        mask = (const int*)d_in[1];
    } else {
        x    = (const float*)d_in[1];
        mask = (const int*)d_in[0];
    }
    float* out = (float*)d_out;

    dim3 g1(NBLK, BATCH);
    pool_k<<<g1, 256>>>(x, mask, out);

    dim3 g2(NBLK / 2, BATCH);
    norm_k<<<g2, 256>>>(out, mask);
}

// round 10
// speedup vs baseline: 1.0332x; 1.0332x over previous
#include <cuda_runtime.h>

#define BATCH  16
#define CHN    64
#define HW     65536
#define HW4    (HW / 4)
#define NTHR   512
#define SUBS   16                   // blocks per batch (barrier arrivals) — R6-proven
#define GRID   (BATCH * SUBS)       // 256 blocks — R6-proven residency
#define CHUNKS 32                   // work chunks per batch, 512 float4 cols each
#define PARK   2                    // chunks parked in SMEM (48 KB)
#define MAXG   8                    // max grabs per block (16*8=128 >= 32: no orphans)

// Per-(batch, chunk) stats, written fresh each launch (no zeroing needed):
// [0]=max_s [1]=max_sq [2]=mean_s [3]=mean_sq [4]=min_s [5]=min_sq [6]=cnt
__device__ float g_cstat[BATCH][CHUNKS][8];
__device__ unsigned g_chunk[BATCH]  = {0};   // chunk tickets (reset at barrier)
__device__ unsigned g_arrive[BATCH] = {0};
__device__ volatile unsigned g_release[BATCH];

__device__ __forceinline__ float warp_sum(float v) {
#pragma unroll
    for (int o = 16; o; o >>= 1) v += __shfl_xor_sync(0xffffffffu, v, o);
    return v;
}

__global__ void __launch_bounds__(NTHR, 2) fused_k(
    const float* __restrict__ x,
    const int*   __restrict__ mask,
    float*       __restrict__ out)
{
    // Dynamic SMEM: PARK chunks x 3 channels x NTHR float4 = 48 KB.
    extern __shared__ float4 sp4[];

    const int b    = blockIdx.x >> 4;       // contiguous map — R6-proven
    const int tid  = threadIdx.x;
    const int lane = tid & 31;
    const int wid  = tid >> 5;

    const float4* xb = reinterpret_cast<const float4*>(x)  + (size_t)b * CHN * HW4;
    const int4*   mb = reinterpret_cast<const int4*>(mask) + (size_t)b * HW4;
    float4*       ob = reinterpret_cast<float4*>(out)      + (size_t)b * 3 * HW4;

    __shared__ unsigned s_chunk;
    __shared__ float sh[16][7];
    int myChunks[MAXG];
    int got = 0;

    // ---------------- Phase 1: steal chunks, pool, per-chunk stats -------------
    while (got < MAXG) {
        __syncthreads();                            // protect s_chunk / sh reuse
        if (tid == 0) s_chunk = atomicAdd(&g_chunk[b], 1u);
        __syncthreads();
        const int c = (int)s_chunk;
        if (c >= CHUNKS) break;

        const int p4 = c * NTHR + tid;
        const float4* xp = xb + p4;

        float4 v = __ldcs(xp);                      // streaming: x is read-once
        float4 vmax = v, vmin = v, vsum = v;
#pragma unroll 8
        for (int ch = 1; ch < CHN; ++ch) {
            float4 t = __ldcs(xp + (size_t)ch * HW4);
            vmax.x = fmaxf(vmax.x, t.x); vmax.y = fmaxf(vmax.y, t.y);
            vmax.z = fmaxf(vmax.z, t.z); vmax.w = fmaxf(vmax.w, t.w);
            vmin.x = fminf(vmin.x, t.x); vmin.y = fminf(vmin.y, t.y);
            vmin.z = fminf(vmin.z, t.z); vmin.w = fminf(vmin.w, t.w);
            vsum.x += t.x; vsum.y += t.y; vsum.z += t.z; vsum.w += t.w;
        }
        const float inv = 1.f / (float)CHN;
        float4 vmean = make_float4(vsum.x * inv, vsum.y * inv, vsum.z * inv, vsum.w * inv);

        if (got < PARK) {
            // Park in SMEM (conflict-free stride-1).
            sp4[(got * 3 + 0) * NTHR + tid] = vmax;
            sp4[(got * 3 + 1) * NTHR + tid] = vmean;
            sp4[(got * 3 + 2) * NTHR + tid] = vmin;
        } else {
            // Overflow (rare): write pre-norm xc to gmem; re-read from L2 later.
            ob[p4]           = vmax;
            ob[HW4 + p4]     = vmean;
            ob[2 * HW4 + p4] = vmin;
        }
        myChunks[got] = c;
        got++;

        // Per-chunk masked stats (deterministic: fixed FP order per chunk).
        int4 mk = mb[p4];
        float m0 = (mk.x == 1) ? 1.f : 0.f;
        float m1 = (mk.y == 1) ? 1.f : 0.f;
        float m2 = (mk.z == 1) ? 1.f : 0.f;
        float m3 = (mk.w == 1) ? 1.f : 0.f;

        float acc[7];
        acc[0] = vmax.x  * m0 + vmax.y  * m1 + vmax.z  * m2 + vmax.w  * m3;
        acc[1] = vmax.x * vmax.x * m0 + vmax.y * vmax.y * m1
               + vmax.z * vmax.z * m2 + vmax.w * vmax.w * m3;
        acc[2] = vmean.x * m0 + vmean.y * m1 + vmean.z * m2 + vmean.w * m3;
        acc[3] = vmean.x * vmean.x * m0 + vmean.y * vmean.y * m1
               + vmean.z * vmean.z * m2 + vmean.w * vmean.w * m3;
        acc[4] = vmin.x  * m0 + vmin.y  * m1 + vmin.z  * m2 + vmin.w  * m3;
        acc[5] = vmin.x * vmin.x * m0 + vmin.y * vmin.y * m1
               + vmin.z * vmin.z * m2 + vmin.w * vmin.w * m3;
        acc[6] = m0 + m1 + m2 + m3;

#pragma unroll
        for (int i = 0; i < 7; ++i) acc[i] = warp_sum(acc[i]);
        if (lane == 0) {
#pragma unroll
            for (int i = 0; i < 7; ++i) sh[wid][i] = acc[i];
        }
        __syncthreads();
        if (wid == 0) {
#pragma unroll
            for (int i = 0; i < 7; ++i) {
                float t = (lane < 16) ? sh[lane][i] : 0.f;
                t = warp_sum(t);
                if (lane == 0) g_cstat[b][c][i] = t;
            }
        }
    }

    // ---------- Per-batch barrier (16 arrivals, self-resetting) — R6-proven ----
    __syncthreads();
    if (tid == 0) {
        __threadfence();                          // publish g_cstat rows
        unsigned phase = g_release[b];
        unsigned old = atomicAdd(&g_arrive[b], 1);
        if (old == SUBS - 1) {
            g_arrive[b] = 0;
            g_chunk[b]  = 0;                      // reset tickets for next launch
            __threadfence();
            g_release[b] = phase + 1;
        } else {
            while (g_release[b] == phase) { __nanosleep(64); }
        }
        __threadfence();
    }
    __syncthreads();

    // ---------------- Final stats: 32 chunks = 32 lanes, fixed order -----------
    __shared__ float s_mean[3], s_rstd[3];
    if (wid == 0) {
        const float4* pr = reinterpret_cast<const float4*>(&g_cstat[b][lane][0]);
        float4 a0 = __ldcg(&pr[0]);   // bypass L1: written by other SMs
        float4 a1 = __ldcg(&pr[1]);
        float s[7] = {a0.x, a0.y, a0.z, a0.w, a1.x, a1.y, a1.z};
#pragma unroll
        for (int i = 0; i < 7; ++i) s[i] = warp_sum(s[i]);
        if (lane == 0) {
            const float cnt = s[6];
#pragma unroll
            for (int ch = 0; ch < 3; ++ch) {
                const float sm   = s[2 * ch];
                const float sq   = s[2 * ch + 1];
                const float mean = sm / cnt;
                const float var  = (sq - sm * mean) / (cnt - 1.f);
                s_mean[ch] = mean;
                s_rstd[ch] = rsqrtf(var);
            }
        }
    }
    __syncthreads();

    const float mean0 = s_mean[0], rstd0 = s_rstd[0];
    const float mean1 = s_mean[1], rstd1 = s_rstd[1];
    const float mean2 = s_mean[2], rstd2 = s_rstd[2];

    // ---------------- Phase 2: normalize my chunks, write final out ------------
#pragma unroll 1
    for (int g = 0; g < got; ++g) {
        const int c  = myChunks[g];
        const int p4 = c * NTHR + tid;
        int4 mk = mb[p4];                          // L2 hit

        float4 v0, v1, v2;
        if (g < PARK) {
            v0 = sp4[(g * 3 + 0) * NTHR + tid];
            v1 = sp4[(g * 3 + 1) * NTHR + tid];
            v2 = sp4[(g * 3 + 2) * NTHR + tid];
        } else {
            v0 = ob[p4];                           // own pre-barrier writes, L2 hit
            v1 = ob[HW4 + p4];
            v2 = ob[2 * HW4 + p4];
        }

        v0.x = (mk.x == 1) ? (v0.x - mean0) * rstd0 : 0.f;
        v0.y = (mk.y == 1) ? (v0.y - mean0) * rstd0 : 0.f;
        v0.z = (mk.z == 1) ? (v0.z - mean0) * rstd0 : 0.f;
        v0.w = (mk.w == 1) ? (v0.w - mean0) * rstd0 : 0.f;

        v1.x = (mk.x == 1) ? (v1.x - mean1) * rstd1 : 0.f;
        v1.y = (mk.y == 1) ? (v1.y - mean1) * rstd1 : 0.f;
        v1.z = (mk.z == 1) ? (v1.z - mean1) * rstd1 : 0.f;
        v1.w = (mk.w == 1) ? (v1.w - mean1) * rstd1 : 0.f;

        v2.x = (mk.x == 1) ? (v2.x - mean2) * rstd2 : 0.f;
        v2.y = (mk.y == 1) ? (v2.y - mean2) * rstd2 : 0.f;
        v2.z = (mk.z == 1) ? (v2.z - mean2) * rstd2 : 0.f;
        v2.w = (mk.w == 1) ? (v2.w - mean2) * rstd2 : 0.f;

        ob[p4]           = v0;
        ob[HW4 + p4]     = v1;
        ob[2 * HW4 + p4] = v2;
    }
}

extern "C" void kernel_launch(void* const* d_in, const int* in_sizes, int n_in,
                              void* d_out, int out_size)
{
    const float* x;
    const int*   mask;
    if (in_sizes[0] > in_sizes[1]) {
        x    = (const float*)d_in[0];
        mask = (const int*)d_in[1];
    } else {
        x    = (const float*)d_in[1];
        mask = (const int*)d_in[0];
    }
    float* out = (float*)d_out;

    const int smem = PARK * 3 * NTHR * sizeof(float4);   // 48 KB dynamic — R6-proven
    static bool configured = false;
    if (!configured) {
        cudaFuncSetAttribute(fused_k, cudaFuncAttributeMaxDynamicSharedMemorySize, smem);
        configured = true;
    }
    fused_k<<<GRID, NTHR, smem>>>(x, mask, out);
}

// round 12
// speedup vs baseline: 1.0351x; 1.0018x over previous
#include <cuda_runtime.h>

#define BATCH 16
#define CHN   64
#define HW    65536
#define HW4   (HW / 4)
#define NBLK  64                     // pool blocks per batch
#define PGRID (BATCH * NBLK)         // 1024 pool blocks (bid 0..1023)
#define NNRM  32                     // norm blocks per batch
#define NGRID (BATCH * NNRM)         // 512 norm blocks (bid 1024..1535)

// Per-(batch, block) partials, written fresh each launch (no zeroing):
__device__ float g_part[BATCH][NBLK][8];
// Final per-batch stats: mean0,rstd0,mean1,rstd1,mean2,rstd2,pad,pad
__device__ float g_stats[BATCH][8];
// Per-batch pool-arrival tickets (reset by last pool block).
__device__ unsigned g_cnt[BATCH] = {0};
// Per-batch stats-ready flags + norm-finish tickets (reset by last norm block).
__device__ volatile unsigned g_done[BATCH];
__device__ unsigned g_nfin[BATCH] = {0};

__device__ __forceinline__ float warp_sum(float v) {
#pragma unroll
    for (int o = 16; o; o >>= 1) v += __shfl_xor_sync(0xffffffffu, v, o);
    return v;
}

__global__ void __launch_bounds__(256) fused_k(
    const float* __restrict__ x,
    const int*   __restrict__ mask,
    float*       __restrict__ out)
{
    const int bid = blockIdx.x;
    const int tid = threadIdx.x;

    if (bid < PGRID) {
        // ================= POOL block (producer): R2/R7 streaming body =========
        const int b   = bid >> 6;
        const int blk = bid & 63;
        const int p4  = blk * 256 + tid;

        const float4* xb = reinterpret_cast<const float4*>(x) + (size_t)b * CHN * HW4 + p4;

        float4 v = __ldcs(&xb[0]);
        float4 vmax = v, vmin = v, vsum = v;
#pragma unroll
        for (int c = 1; c < CHN; ++c) {
            float4 t = __ldcs(&xb[(size_t)c * HW4]);
            vmax.x = fmaxf(vmax.x, t.x); vmax.y = fmaxf(vmax.y, t.y);
            vmax.z = fmaxf(vmax.z, t.z); vmax.w = fmaxf(vmax.w, t.w);
            vmin.x = fminf(vmin.x, t.x); vmin.y = fminf(vmin.y, t.y);
            vmin.z = fminf(vmin.z, t.z); vmin.w = fminf(vmin.w, t.w);
            vsum.x += t.x; vsum.y += t.y; vsum.z += t.z; vsum.w += t.w;
        }
        const float inv = 1.f / (float)CHN;
        float4 vmean = make_float4(vsum.x * inv, vsum.y * inv, vsum.z * inv, vsum.w * inv);

        float4* ob = reinterpret_cast<float4*>(out) + (size_t)b * 3 * HW4 + p4;
        ob[0]       = vmax;
        ob[HW4]     = vmean;
        ob[2 * HW4] = vmin;

        int4 mk = reinterpret_cast<const int4*>(mask)[(size_t)b * HW4 + p4];
        float m0 = (mk.x == 1) ? 1.f : 0.f;
        float m1 = (mk.y == 1) ? 1.f : 0.f;
        float m2 = (mk.z == 1) ? 1.f : 0.f;
        float m3 = (mk.w == 1) ? 1.f : 0.f;

        float vals[7];
        vals[0] = vmax.x  * m0 + vmax.y  * m1 + vmax.z  * m2 + vmax.w  * m3;
        vals[1] = vmax.x * vmax.x * m0 + vmax.y * vmax.y * m1
                + vmax.z * vmax.z * m2 + vmax.w * vmax.w * m3;
        vals[2] = vmean.x * m0 + vmean.y * m1 + vmean.z * m2 + vmean.w * m3;
        vals[3] = vmean.x * vmean.x * m0 + vmean.y * vmean.y * m1
                + vmean.z * vmean.z * m2 + vmean.w * vmean.w * m3;
        vals[4] = vmin.x  * m0 + vmin.y  * m1 + vmin.z  * m2 + vmin.w  * m3;
        vals[5] = vmin.x * vmin.x * m0 + vmin.y * vmin.y * m1
                + vmin.z * vmin.z * m2 + vmin.w * vmin.w * m3;
        vals[6] = m0 + m1 + m2 + m3;

        __shared__ float sh[8][7];
        const int lane = tid & 31;
        const int wid  = tid >> 5;

#pragma unroll
        for (int i = 0; i < 7; ++i) vals[i] = warp_sum(vals[i]);
        if (lane == 0) {
#pragma unroll
            for (int i = 0; i < 7; ++i) sh[wid][i] = vals[i];
        }
        __syncthreads();
        if (wid == 0) {
#pragma unroll
            for (int i = 0; i < 7; ++i) {
                float t = (lane < 8) ? sh[lane][i] : 0.f;
                t = warp_sum(t);
                if (lane == 0) g_part[b][blk][i] = t;
            }

            // ---- last pool block of this batch finalizes mean/rstd ----
            unsigned old = 0;
            if (lane == 0) {
                __threadfence();
                old = atomicAdd(&g_cnt[b], 1);
            }
            old = __shfl_sync(0xffffffffu, old, 0);
            if (old == NBLK - 1) {
                __threadfence();
                // Deterministic fixed-order reduce: lane r sums rows r, r+32.
                const float4* r0 = reinterpret_cast<const float4*>(&g_part[b][lane][0]);
                const float4* r1 = reinterpret_cast<const float4*>(&g_part[b][lane + 32][0]);
                float4 a0 = __ldcg(&r0[0]), a1 = __ldcg(&r0[1]);
                float4 b0 = __ldcg(&r1[0]), b1 = __ldcg(&r1[1]);
                float s[7];
                s[0] = a0.x + b0.x; s[1] = a0.y + b0.y; s[2] = a0.z + b0.z;
                s[3] = a0.w + b0.w; s[4] = a1.x + b1.x; s[5] = a1.y + b1.y;
                s[6] = a1.z + b1.z;
#pragma unroll
                for (int i = 0; i < 7; ++i) s[i] = warp_sum(s[i]);
                if (lane == 0) {
                    const float cnt = s[6];
#pragma unroll
                    for (int ch = 0; ch < 3; ++ch) {
                        const float sm   = s[2 * ch];
                        const float sq   = s[2 * ch + 1];
                        const float mean = sm / cnt;
                        const float var  = (sq - sm * mean) / (cnt - 1.f);
                        g_stats[b][2 * ch]     = mean;
                        g_stats[b][2 * ch + 1] = rsqrtf(var);
                    }
                    g_cnt[b] = 0;                 // self-reset tickets
                    __threadfence();
                    g_done[b] = 1;                // publish stats-ready
                }
            }
        }
    } else {
        // ================= NORM block (consumer): waits for its batch ==========
        const int nb  = bid - PGRID;
        const int b   = nb >> 5;
        const int blk = nb & 31;

        // Spin until this batch's stats are published. Pool blocks never wait,
        // so they always progress/retire -> no deadlock regardless of residency.
        if (tid == 0) {
            while (g_done[b] == 0u) { __nanosleep(128); }
        }
        __syncthreads();
        __threadfence();   // acquire g_stats

        const float4* st4 = reinterpret_cast<const float4*>(&g_stats[b][0]);
        float4 s0 = __ldcg(&st4[0]);
        float4 s1 = __ldcg(&st4[1]);
        const float mean0 = s0.x, rstd0 = s0.y;
        const float mean1 = s0.z, rstd1 = s0.w;
        const float mean2 = s1.x, rstd2 = s1.y;

        const int pA = blk * 512 + tid;
        const int pB = pA + 256;

        const int4* mb = reinterpret_cast<const int4*>(mask) + (size_t)b * HW4;
        float4*     ob = reinterpret_cast<float4*>(out)      + (size_t)b * 3 * HW4;

        int4 mkA = mb[pA];
        int4 mkB = mb[pB];
        float4 a0 = ob[pA];             float4 b0 = ob[pB];
        float4 a1 = ob[HW4 + pA];       float4 b1 = ob[HW4 + pB];
        float4 a2 = ob[2 * HW4 + pA];   float4 b2 = ob[2 * HW4 + pB];

        a0.x = (mkA.x == 1) ? (a0.x - mean0) * rstd0 : 0.f;
        a0.y = (mkA.y == 1) ? (a0.y - mean0) * rstd0 : 0.f;
        a0.z = (mkA.z == 1) ? (a0.z - mean0) * rstd0 : 0.f;
        a0.w = (mkA.w == 1) ? (a0.w - mean0) * rstd0 : 0.f;
        a1.x = (mkA.x == 1) ? (a1.x - mean1) * rstd1 : 0.f;
        a1.y = (mkA.y == 1) ? (a1.y - mean1) * rstd1 : 0.f;
        a1.z = (mkA.z == 1) ? (a1.z - mean1) * rstd1 : 0.f;
        a1.w = (mkA.w == 1) ? (a1.w - mean1) * rstd1 : 0.f;
        a2.x = (mkA.x == 1) ? (a2.x - mean2) * rstd2 : 0.f;
        a2.y = (mkA.y == 1) ? (a2.y - mean2) * rstd2 : 0.f;
        a2.z = (mkA.z == 1) ? (a2.z - mean2) * rstd2 : 0.f;
        a2.w = (mkA.w == 1) ? (a2.w - mean2) * rstd2 : 0.f;

        b0.x = (mkB.x == 1) ? (b0.x - mean0) * rstd0 : 0.f;
        b0.y = (mkB.y == 1) ? (b0.y - mean0) * rstd0 : 0.f;
        b0.z = (mkB.z == 1) ? (b0.z - mean0) * rstd0 : 0.f;
        b0.w = (mkB.w == 1) ? (b0.w - mean0) * rstd0 : 0.f;
        b1.x = (mkB.x == 1) ? (b1.x - mean1) * rstd1 : 0.f;
        b1.y = (mkB.y == 1) ? (b1.y - mean1) * rstd1 : 0.f;
        b1.z = (mkB.z == 1) ? (b1.z - mean1) * rstd1 : 0.f;
        b1.w = (mkB.w == 1) ? (b1.w - mean1) * rstd1 : 0.f;
        b2.x = (mkB.x == 1) ? (b2.x - mean2) * rstd2 : 0.f;
        b2.y = (mkB.y == 1) ? (b2.y - mean2) * rstd2 : 0.f;
        b2.z = (mkB.z == 1) ? (b2.z - mean2) * rstd2 : 0.f;
        b2.w = (mkB.w == 1) ? (b2.w - mean2) * rstd2 : 0.f;

        ob[pA]           = a0;   ob[pB]           = b0;
        ob[HW4 + pA]     = a1;   ob[HW4 + pB]     = b1;
        ob[2 * HW4 + pA] = a2;   ob[2 * HW4 + pB] = b2;

        // Last norm block of this batch resets the flag for the next launch.
        __syncthreads();
        if (tid == 0) {
            unsigned old = atomicAdd(&g_nfin[b], 1);
            if (old == NNRM - 1) {
                g_nfin[b] = 0;
                g_done[b] = 0;
            }
        }
    }
}

extern "C" void kernel_launch(void* const* d_in, const int* in_sizes, int n_in,
                              void* d_out, int out_size)
{
    const float* x;
    const int*   mask;
    if (in_sizes[0] > in_sizes[1]) {
        x    = (const float*)d_in[0];
        mask = (const int*)d_in[1];
    } else {
        x    = (const float*)d_in[1];
        mask = (const int*)d_in[0];
    }
    float* out = (float*)d_out;

    fused_k<<<PGRID + NGRID, 256>>>(x, mask, out);
}